// round 13
// baseline (speedup 1.0000x reference)
#include <cuda_runtime.h>
#include <cstdint>

#define H 512
#define W 512
#define HW 2

// ---- fused kernel geometry ----
#define OT   64                 // output tile (square)
#define ST   72                 // smem row stride (words)
#define INR  70                 // input halo region size (halo 3)
#define RG   68                 // pass1/pass2 region size (halo 2)
#define NTHR 289                // 17 x 17

// ---- fallback (full 5x5 persistent) geometry ----
#define BX 32
#define BY 4
#define PPT 8
#define BLKY (BY * PPT)
#define TILE_W (BX + 2*HW)
#define TILE_H (BLKY + 2*HW)
#define FB_GRID 296

typedef unsigned long long u64;

// scratch for the fallback path only
__device__ float g_buf0[32 * H * W];
__device__ float g_buf1[32 * H * W];

__device__ __forceinline__ float ex2_approx(float x) {
    float y;
    asm("ex2.approx.ftz.f32 %0, %1;" : "=f"(y) : "f"(x));
    return y;
}
__device__ __forceinline__ u64 pack2(float lo, float hi) {
    u64 r; asm("mov.b64 %0, {%1, %2};" : "=l"(r) : "f"(lo), "f"(hi)); return r;
}
__device__ __forceinline__ void unpack2(u64 v, float& lo, float& hi) {
    asm("mov.b64 {%0, %1}, %2;" : "=f"(lo), "=f"(hi) : "l"(v));
}
__device__ __forceinline__ u64 fma2(u64 a, u64 b, u64 c) {
    u64 r; asm("fma.rn.f32x2 %0, %1, %2, %3;" : "=l"(r) : "l"(a), "l"(b), "l"(c)); return r;
}
__device__ __forceinline__ u64 add2(u64 a, u64 b) {
    u64 r; asm("add.rn.f32x2 %0, %1, %2;" : "=l"(r) : "l"(a), "l"(b)); return r;
}
__device__ __forceinline__ u64 mul2(u64 a, u64 b) {
    u64 r; asm("mul.rn.f32x2 %0, %1, %2;" : "=l"(r) : "l"(a), "l"(b)); return r;
}

// all three passes satisfy the 3x3 truncation bound?
// per dropped tap err <= ws * sr * e^{-1/2}; den >= 1 (uniform across launch)
__device__ __forceinline__ bool all_fast(const float* __restrict__ sxyz,
                                         const float* __restrict__ srr) {
    bool fast = true;
    #pragma unroll
    for (int p = 0; p < 3; p++) {
        float sx = sxyz[2*p], sy = sxyz[2*p+1], sr = srr[p];
        float axn = 0.5f/(sx*sx), ayn = 0.5f/(sy*sy);
        float w1x = __expf(-axn), w4x = __expf(-4.f*axn);
        float w1y = __expf(-ayn), w4y = __expf(-4.f*ayn);
        float ring = 2.f*w4x*(1.f+2.f*w1y+2.f*w4y) + 2.f*w4y*(1.f+2.f*w1x);
        if (!(ring * 0.6065307f * sr < 1e-4f)) fast = false;
    }
    return fast;
}

// ---- the proven 3x3 packed inner loop: 4-wide x 4-tall, src/dst by pointer ----
__device__ __forceinline__ void bilat4(
    const float* src, int sstr,      // src[0] = window top-left of first px row
    float* dst, int dstr,            // dst += r*dstr, float4 stores (16B aligned)
    float axl, float ayl, float nar)
{
    const float axyl = axl + ayl;
    const u64 nar2    = pack2(nar, nar);
    const u64 negone2 = pack2(-1.0f, -1.0f);
    const u64 one2    = pack2(1.0f, 1.0f);
    const u64 ns_xy2  = pack2(-axyl, -axyl);
    const u64 ns_y2   = pack2(-ayl,  -ayl);
    const u64 ns_x2   = pack2(-axl,  -axl);

    float rows[4][6];
    #pragma unroll
    for (int j = 0; j < 6; j++) rows[0][j] = src[j];
    #pragma unroll
    for (int j = 0; j < 6; j++) rows[1][j] = src[sstr + j];
    #pragma unroll
    for (int j = 0; j < 6; j++) rows[2][j] = src[2*sstr + j];

    #define EDGE2(W2, NB2, NS2, C2) {                    \
        const u64 d2 = fma2((C2), negone2, (NB2));       \
        const u64 u2 = mul2(d2, nar2);                   \
        const u64 g2 = fma2(d2, u2, (NS2));              \
        float ga, gb;  unpack2(g2, ga, gb);              \
        (W2) = pack2(ex2_approx(ga), ex2_approx(gb));    \
    }
    #define APPLY(W2, NB2, NUM2, DEN2) {                 \
        (NUM2) = fma2((W2), (NB2), (NUM2));              \
        (DEN2) = add2((DEN2), (W2));                     \
    }

    u64 wm1A, w0A, wp1A, wm1B, w0B, wp1B;

    #pragma unroll
    for (int r = 0; r < 4; r++) {
        if (r < 3) {
            #pragma unroll
            for (int j = 0; j < 6; j++) rows[(r+3)&3][j] = src[(r+3)*sstr + j];
        }
        const float* top = rows[(r    ) & 3];
        const float* mid = rows[(r + 1) & 3];
        const float* bot = rows[(r + 2) & 3];

        const u64 c2A = pack2(mid[1], mid[2]);
        const u64 c2B = pack2(mid[3], mid[4]);
        u64 numA = c2A, denA = one2;
        u64 numB = c2B, denB = one2;

        const u64 t_m1A = pack2(top[0], top[1]);
        const u64 t_0A  = pack2(top[1], top[2]);
        const u64 t_p1A = pack2(top[2], top[3]);
        const u64 t_m1B = t_p1A;
        const u64 t_0B  = pack2(top[3], top[4]);
        const u64 t_p1B = pack2(top[4], top[5]);

        if (r == 0) {
            u64 w;
            EDGE2(w, t_m1A, ns_xy2, c2A) APPLY(w, t_m1A, numA, denA)
            EDGE2(w, t_0A,  ns_y2,  c2A) APPLY(w, t_0A,  numA, denA)
            EDGE2(w, t_p1A, ns_xy2, c2A) APPLY(w, t_p1A, numA, denA)
            EDGE2(w, t_m1B, ns_xy2, c2B) APPLY(w, t_m1B, numB, denB)
            EDGE2(w, t_0B,  ns_y2,  c2B) APPLY(w, t_0B,  numB, denB)
            EDGE2(w, t_p1B, ns_xy2, c2B) APPLY(w, t_p1B, numB, denB)
        } else {
            APPLY(w0A, t_0A, numA, denA)
            APPLY(w0B, t_0B, numB, denB)
            const float df1 = top[0] - mid[1];
            const float wf1 = ex2_approx(fmaf(df1, df1 * nar, -axyl));
            const float df2 = top[5] - mid[4];
            const float wf2 = ex2_approx(fmaf(df2, df2 * nar, -axyl));
            float m1Alo, m1Ahi, m1Blo, m1Bhi, p1Alo, p1Ahi, p1Blo, p1Bhi;
            unpack2(wm1A, m1Alo, m1Ahi);
            unpack2(wm1B, m1Blo, m1Bhi);
            unpack2(wp1A, p1Alo, p1Ahi);
            unpack2(wp1B, p1Blo, p1Bhi);
            { const u64 w2 = pack2(wf1,   p1Alo); APPLY(w2, t_m1A, numA, denA) }
            { const u64 w2 = pack2(p1Ahi, p1Blo); APPLY(w2, t_m1B, numB, denB) }
            { const u64 w2 = pack2(m1Ahi, m1Blo); APPLY(w2, t_p1A, numA, denA) }
            { const u64 w2 = pack2(m1Bhi, wf2);   APPLY(w2, t_p1B, numB, denB) }
        }

        // mid row: 5 distinct horizontal edges
        {
            const u64 nbAl = pack2(mid[0], mid[1]);
            const u64 nbAr = pack2(mid[2], mid[3]);
            const u64 nbBr = pack2(mid[4], mid[5]);

            const u64 dP = fma2(c2A, negone2, nbAl);
            const u64 gP = fma2(dP, mul2(dP, nar2), ns_x2);
            float gPl, gPh;  unpack2(gP, gPl, gPh);
            const float wPl = ex2_approx(gPl), wPh = ex2_approx(gPh);

            const u64 dQ = fma2(c2B, negone2, nbAr);
            const u64 gQ = fma2(dQ, mul2(dQ, nar2), ns_x2);
            float gQl, gQh;  unpack2(gQ, gQl, gQh);
            const float wQl = ex2_approx(gQl), wQh = ex2_approx(gQh);

            const float d34 = mid[5] - mid[4];
            const float w34 = ex2_approx(fmaf(d34, d34 * nar, -axl));

            const u64 LA = pack2(wPl, wPh);
            const u64 RA = pack2(wPh, wQl);
            const u64 LB = pack2(wQl, wQh);
            const u64 RB = pack2(wQh, w34);
            APPLY(LA, nbAl, numA, denA)
            APPLY(RA, nbAr, numA, denA)
            APPLY(LB, nbAr, numB, denB)
            APPLY(RB, nbBr, numB, denB)
        }

        // bot row (fresh; cache for next iteration)
        {
            const u64 b_m1A = pack2(bot[0], bot[1]);
            const u64 b_0A  = pack2(bot[1], bot[2]);
            const u64 b_p1A = pack2(bot[2], bot[3]);
            const u64 b_m1B = b_p1A;
            const u64 b_0B  = pack2(bot[3], bot[4]);
            const u64 b_p1B = pack2(bot[4], bot[5]);
            EDGE2(wm1A, b_m1A, ns_xy2, c2A) APPLY(wm1A, b_m1A, numA, denA)
            EDGE2(w0A,  b_0A,  ns_y2,  c2A) APPLY(w0A,  b_0A,  numA, denA)
            EDGE2(wp1A, b_p1A, ns_xy2, c2A) APPLY(wp1A, b_p1A, numA, denA)
            EDGE2(wm1B, b_m1B, ns_xy2, c2B) APPLY(wm1B, b_m1B, numB, denB)
            EDGE2(w0B,  b_0B,  ns_y2,  c2B) APPLY(w0B,  b_0B,  numB, denB)
            EDGE2(wp1B, b_p1B, ns_xy2, c2B) APPLY(wp1B, b_p1B, numB, denB)
        }

        float n0, n1, n2, n3, d0, d1, d2, d3;
        unpack2(numA, n0, n1); unpack2(denA, d0, d1);
        unpack2(numB, n2, n3); unpack2(denB, d2, d3);
        float4 res;
        res.x = __fdividef(n0, d0);
        res.y = __fdividef(n1, d1);
        res.z = __fdividef(n2, d2);
        res.w = __fdividef(n3, d3);
        *(float4*)(dst + r * dstr) = res;
    }
    #undef EDGE2
    #undef APPLY
}

// replicate pad semantics into the virtual halo of a 68x68 region buffer
// region row r <=> y = gy0-2+r ; region col c <=> x = gx0-2+c
__device__ __forceinline__ void fixup_region(float* R, int gx0, int gy0, int t) {
    if (gy0 == 0) {
        for (int i = t; i < 2 * RG; i += NTHR) {
            int rr = i / RG, cc = i - rr * RG;
            R[rr * ST + cc] = R[2 * ST + cc];
        }
    }
    if (gy0 + OT == H) {
        for (int i = t; i < 2 * RG; i += NTHR) {
            int rr = i / RG, cc = i - rr * RG;
            R[(66 + rr) * ST + cc] = R[65 * ST + cc];
        }
    }
    __syncthreads();
    if (gx0 == 0) {
        for (int i = t; i < 2 * RG; i += NTHR) {
            int cc = i / RG, rr = i - cc * RG;
            R[rr * ST + cc] = R[rr * ST + 2];
        }
    }
    if (gx0 + OT == W) {
        for (int i = t; i < 2 * RG; i += NTHR) {
            int cc = i / RG, rr = i - cc * RG;
            R[rr * ST + 66 + cc] = R[rr * ST + 65];
        }
    }
    __syncthreads();
}

// ---------------- fused 3-pass kernel (fast 3x3 mode) ----------------
__global__ __launch_bounds__(NTHR, 3) void bilateral_fused(
    const float* __restrict__ in, float* __restrict__ out,
    const float* __restrict__ sigma_xyz, const float* __restrict__ sigma_r)
{
    if (!all_fast(sigma_xyz, sigma_r)) return;   // fallback kernels handle it

    // sA: IN (70x72), later reused as P2 (68x72). sB: P1 (68x72 + slack for
    // pass2's harmless over/under-reads at region edges).
    __shared__ float smem[INR * ST + INR * ST];
    float* sA = smem;
    float* sB = smem + INR * ST;

    const int b   = blockIdx.z;
    const int gx0 = blockIdx.x * OT;
    const int gy0 = blockIdx.y * OT;
    const int s   = threadIdx.x;     // 0..16 column strip
    const int g   = threadIdx.y;     // 0..16 row group
    const int t   = g * 17 + s;

    const float* img = in  + (size_t)b * (H * W);
    float*       op  = out + (size_t)b * (H * W);

    // ---- load input halo 70x70 (clamped => exact replicate padding) ----
    for (int idx = t; idx < INR * INR; idx += NTHR) {
        int rr = idx / INR, cc = idx - rr * INR;
        int gx = min(max(gx0 - 3 + cc, 0), W - 1);
        int gy = min(max(gy0 - 3 + rr, 0), H - 1);
        sA[rr * ST + cc] = img[gy * W + gx];
    }
    __syncthreads();

    const float LOG2E = 1.4426950408889634f;

    // ---- pass 1: sA (IN) -> sB (P1), region 68x68 ----
    {
        const float sx = sigma_xyz[0], sy = sigma_xyz[1], sr = sigma_r[0];
        const float axl = 0.5f/(sx*sx) * LOG2E;
        const float ayl = 0.5f/(sy*sy) * LOG2E;
        const float nar = -(0.5f/(sr*sr)) * LOG2E;
        // px region rows 4g..4g+3, cols 4s..4s+3; IN row of window top = 4g
        bilat4(sA + (4*g) * ST + 4*s, ST, sB + (4*g) * ST + 4*s, ST, axl, ayl, nar);
    }
    __syncthreads();
    fixup_region(sB, gx0, gy0, t);

    // ---- pass 2: sB (P1) -> sA (P2), region 68x68 ----
    {
        const float sx = sigma_xyz[2], sy = sigma_xyz[3], sr = sigma_r[1];
        const float axl = 0.5f/(sx*sx) * LOG2E;
        const float ayl = 0.5f/(sy*sy) * LOG2E;
        const float nar = -(0.5f/(sr*sr)) * LOG2E;
        // window top row = (4g)-1, left col = (4s)-1 (edge over/under-reads
        // stay inside the combined smem block and feed only discarded ring px)
        bilat4(sB + (4*g - 1) * ST + (4*s - 1), ST, sA + (4*g) * ST + 4*s, ST, axl, ayl, nar);
    }
    __syncthreads();
    fixup_region(sA, gx0, gy0, t);

    // ---- pass 3: sA (P2) -> gmem, 64x64 ----
    if (s < 16 && g < 16) {
        const float sx = sigma_xyz[4], sy = sigma_xyz[5], sr = sigma_r[2];
        const float axl = 0.5f/(sx*sx) * LOG2E;
        const float ayl = 0.5f/(sy*sy) * LOG2E;
        const float nar = -(0.5f/(sr*sr)) * LOG2E;
        // px (x,y) -> region (x+2, y+2); window top = region row (4g+2)-1
        bilat4(sA + (4*g + 1) * ST + (4*s + 1), ST,
               op + (gy0 + 4*g) * W + gx0 + 4*s, W, axl, ayl, nar);
    }
}

// ---------------- fallback: exact full 5x5, persistent grid-stride ----------------
__global__ __launch_bounds__(BX * BY) void bilateral_full5x5(
    const float* __restrict__ in, float* __restrict__ out,
    const float* __restrict__ sigma_xyz, const float* __restrict__ sigma_r,
    int pass, int batch)
{
    if (all_fast(sigma_xyz, sigma_r)) return;   // fused kernel handled it

    __shared__ float tile[TILE_H][TILE_W];

    const float LOG2E = 1.4426950408889634f;
    const float sx = sigma_xyz[2 * pass + 0];
    const float sy = sigma_xyz[2 * pass + 1];
    const float sr = sigma_r[pass];
    const float axl = 0.5f / (sx * sx) * LOG2E;
    const float ayl = 0.5f / (sy * sy) * LOG2E;
    const float ar  = (0.5f / (sr * sr)) * LOG2E;
    const float nar = -ar;
    const float twoar = 2.0f * ar;
    const float axyl = axl + ayl;
    const float a4x = 4.f * axl, a4y = 4.f * ayl;

    const int tiles_x = W / BX;
    const int tiles_y = H / BLKY;
    const int tile_total = tiles_x * tiles_y * batch;
    const int t = threadIdx.y * BX + threadIdx.x;
    const int tx = threadIdx.x;
    const int y0 = threadIdx.y * PPT;
    const int cx = tx + HW;

    for (int tid = blockIdx.x; tid < tile_total; tid += gridDim.x) {
        const int b   = tid / (tiles_x * tiles_y);
        const int rem = tid - b * (tiles_x * tiles_y);
        const int bx = (rem % tiles_x) * BX;
        const int by = (rem / tiles_x) * BLKY;
        const float* img = in + (size_t)b * (H * W);

        __syncthreads();
        #pragma unroll
        for (int k = 0; k < (TILE_W * TILE_H + BX*BY - 1) / (BX*BY); k++) {
            int idx = t + k * (BX * BY);
            if (idx < TILE_W * TILE_H) {
                int ly = idx / TILE_W;
                int lx = idx - ly * TILE_W;
                int gx = min(max(bx + lx - HW, 0), W - 1);
                int gy = min(max(by + ly - HW, 0), H - 1);
                tile[ly][lx] = img[gy * W + gx];
            }
        }
        __syncthreads();

        float* orow = out + (size_t)b * (H * W) + (by + y0) * W + (bx + tx);

        #define TAP(NB, T0C) {                                   \
            const float nb = (NB);                               \
            const float u  = fmaf(nb, nar, t1);                  \
            const float w  = ex2_approx(fmaf(nb, u, (T0C)));     \
            num0 = fmaf(w, nb, num0);                            \
            den0 += w;                                           \
        }
        #define TAP2(NB, T0C) {                                  \
            const float nb = (NB);                               \
            const float u  = fmaf(nb, nar, t1);                  \
            const float w  = ex2_approx(fmaf(nb, u, (T0C)));     \
            num1 = fmaf(w, nb, num1);                            \
            den1 += w;                                           \
        }

        #pragma unroll
        for (int r = 0; r < PPT; r++) {
            const int py = y0 + HW + r;
            const float c  = tile[py][cx];
            const float t1 = twoar * c;
            const float t0 = nar * c * c;
            const float t10 = t0 - axl;
            const float t01 = t0 - ayl;
            const float t11 = t0 - axyl;
            const float t20 = t0 - a4x;
            const float t02 = t0 - a4y;
            const float t21 = t0 - (a4x + ayl);
            const float t12 = t0 - (axl + a4y);
            const float t22 = t0 - (a4x + a4y);

            float num0 = c,   den0 = 1.0f;
            float num1 = 0.f, den1 = 0.0f;

            #define DO_S(DY, DX, T0C)  TAP (tile[py + (DY)][cx + (DX)], T0C)
            #define DO_S2(DY, DX, T0C) TAP2(tile[py + (DY)][cx + (DX)], T0C)
            DO_S (-2,-2,t22) DO_S2(-2,-1,t12) DO_S (-2,0,t02) DO_S2(-2,1,t12) DO_S (-2,2,t22)
            DO_S2(-1,-2,t21) DO_S (-1,-1,t11) DO_S2(-1,0,t01) DO_S (-1,1,t11) DO_S2(-1,2,t21)
            DO_S ( 0,-2,t20) DO_S2( 0,-1,t10)                 DO_S2( 0,1,t10) DO_S ( 0,2,t20)
            DO_S2( 1,-2,t21) DO_S ( 1,-1,t11) DO_S2( 1,0,t01) DO_S ( 1,1,t11) DO_S2( 1,2,t21)
            DO_S ( 2,-2,t22) DO_S2( 2,-1,t12) DO_S ( 2,0,t02) DO_S2( 2,1,t12) DO_S ( 2,2,t22)
            #undef DO_S
            #undef DO_S2

            orow[r * W] = __fdividef(num0 + num1, den0 + den1);
        }
        #undef TAP
        #undef TAP2
    }
}

extern "C" void kernel_launch(void* const* d_in, const int* in_sizes, int n_in,
                              void* d_out, int out_size)
{
    const float* x         = (const float*)d_in[0];
    const float* sigma_xyz = (const float*)d_in[1];
    const float* sigma_r   = (const float*)d_in[2];
    float* out = (float*)d_out;

    const int B = in_sizes[0] / (H * W);

    float* buf0;
    float* buf1;
    cudaGetSymbolAddress((void**)&buf0, g_buf0);
    cudaGetSymbolAddress((void**)&buf1, g_buf1);

    // fast mode: one fused kernel does all 3 passes via smem
    dim3 fblock(17, 17, 1);
    dim3 fgrid(W / OT, H / OT, B);
    bilateral_fused<<<fgrid, fblock>>>(x, out, sigma_xyz, sigma_r);

    // fallback mode (general sigmas): exact 5x5, persistent; no-ops in fast mode
    dim3 block(BX, BY, 1);
    bilateral_full5x5<<<FB_GRID, block>>>(x,    buf0, sigma_xyz, sigma_r, 0, B);
    bilateral_full5x5<<<FB_GRID, block>>>(buf0, buf1, sigma_xyz, sigma_r, 1, B);
    bilateral_full5x5<<<FB_GRID, block>>>(buf1, out,  sigma_xyz, sigma_r, 2, B);
}

// round 14
// speedup vs baseline: 1.3472x; 1.3472x over previous
#include <cuda_runtime.h>
#include <cstdint>

#define HW 2
#define H 512
#define W 512

// ---- geometry: 4-wide x 8-tall per thread, direct gmem ----
#define GTX 8                        // threads x (each covers 4 px)
#define GTY 8                        // threads y
#define FPPT 8                       // pixel rows per thread
#define GBLKX 32                     // px per block in x
#define GBLKY (GTY * FPPT)           // 64 px per block in y

typedef unsigned long long u64;

// scratch (allocation-free rule -> device globals)
__device__ float g_buf0[32 * H * W];
__device__ float g_buf1[32 * H * W];

__device__ __forceinline__ float ex2_approx(float x) {
    float y;
    asm("ex2.approx.ftz.f32 %0, %1;" : "=f"(y) : "f"(x));
    return y;
}

// packed f32x2 helpers (Blackwell FFMA2/FADD2/FMUL2 — only reachable via PTX)
__device__ __forceinline__ u64 pack2(float lo, float hi) {
    u64 r;
    asm("mov.b64 %0, {%1, %2};" : "=l"(r) : "f"(lo), "f"(hi));
    return r;
}
__device__ __forceinline__ void unpack2(u64 v, float& lo, float& hi) {
    asm("mov.b64 {%0, %1}, %2;" : "=f"(lo), "=f"(hi) : "l"(v));
}
__device__ __forceinline__ u64 fma2(u64 a, u64 b, u64 c) {
    u64 r;
    asm("fma.rn.f32x2 %0, %1, %2, %3;" : "=l"(r) : "l"(a), "l"(b), "l"(c));
    return r;
}
__device__ __forceinline__ u64 add2(u64 a, u64 b) {
    u64 r;
    asm("add.rn.f32x2 %0, %1, %2;" : "=l"(r) : "l"(a), "l"(b));
    return r;
}
__device__ __forceinline__ u64 mul2(u64 a, u64 b) {
    u64 r;
    asm("mul.rn.f32x2 %0, %1, %2;" : "=l"(r) : "l"(a), "l"(b));
    return r;
}

// ---------------- single kernel: adaptive 3x3 fast path + cold full-5x5 path ----------------
__global__ __launch_bounds__(GTX * GTY) void bilateral_pass(
    const float* __restrict__ in, float* __restrict__ out,
    const float* __restrict__ sigma_xyz, const float* __restrict__ sigma_r,
    int pass)
{
    const float LOG2E = 1.4426950408889634f;
    const float sx = sigma_xyz[2 * pass + 0];
    const float sy = sigma_xyz[2 * pass + 1];
    const float sr = sigma_r[pass];

    const float axn = 0.5f / (sx * sx);
    const float ayn = 0.5f / (sy * sy);
    const float axl = axn * LOG2E;               // log2-domain spatial coeffs
    const float ayl = ayn * LOG2E;
    const float ar  = (0.5f / (sr * sr)) * LOG2E;
    const float nar = -ar;
    const float axyl = axl + ayl;

    const int b   = blockIdx.z;
    const int gx0 = blockIdx.x * GBLKX + threadIdx.x * 4;     // first pixel col
    const int gy0 = blockIdx.y * GBLKY + threadIdx.y * FPPT;  // first pixel row
    const float* img = in  + (size_t)b * (H * W);
    float*       op  = out + (size_t)b * (H * W);

    // ---- adaptive truncation decision (uniform across launch) ----
    // error bound for dropping the 16 |d|=2 taps: per tap <= ws * sr * e^{-1/2}; den >= 1.
    {
        const float w1x = __expf(-axn), w4x = __expf(-4.f * axn);
        const float w1y = __expf(-ayn), w4y = __expf(-4.f * ayn);
        const float ring = 2.f * w4x * (1.f + 2.f * w1y + 2.f * w4y)
                         + 2.f * w4y * (1.f + 2.f * w1x);
        if (!(ring * 0.6065307f * sr < 1e-4f)) {
            // -------- cold path: exact full 5x5, direct gmem, minimal registers --------
            #pragma unroll 1
            for (int r = 0; r < FPPT; r++) {
                #pragma unroll 1
                for (int i = 0; i < 4; i++) {
                    const int py = gy0 + r, px = gx0 + i;
                    const float c = img[py * W + px];
                    float num = c, den = 1.0f;
                    #pragma unroll 1
                    for (int dy = -2; dy <= 2; dy++) {
                        const int yy = min(max(py + dy, 0), H - 1);
                        #pragma unroll 1
                        for (int dx = -2; dx <= 2; dx++) {
                            if ((dx | dy) == 0) continue;
                            const int xx = min(max(px + dx, 0), W - 1);
                            const float nb = img[yy * W + xx];
                            const float d  = nb - c;
                            const float s  = fmaf((float)(dx * dx), axl,
                                                  (float)(dy * dy) * ayl);
                            const float w  = ex2_approx(fmaf(d * d, nar, -s));
                            num = fmaf(w, nb, num);
                            den += w;
                        }
                    }
                    op[py * W + px] = __fdividef(num, den);
                }
            }
            return;
        }
    }

    // -------- fast path: 3x3, packed taps + symmetric-edge weight caches --------
    const u64 nar2    = pack2(nar, nar);
    const u64 negone2 = pack2(-1.0f, -1.0f);
    const u64 one2    = pack2(1.0f, 1.0f);
    const u64 ns_xy2  = pack2(-axyl, -axyl);   // |dx|=1,|dy|=1
    const u64 ns_y2   = pack2(-ayl,  -ayl);    // dx=0,|dy|=1
    const u64 ns_x2   = pack2(-axl,  -axl);    // |dx|=1,dy=0

    // clamped edge columns (only ones that can go OOB)
    const int xm1 = max(gx0 - 1, 0);
    const int xp4 = min(gx0 + 4, W - 1);

    // 4-slot row ring, 6 floats per row (cols gx0-1 .. gx0+4)
    float rows[4][6];

    #define LOAD_ROW(SLOT, RY) {                                        \
        const int ryc = min(max((RY), 0), H - 1);                       \
        const float* rp = img + ryc * W;                                \
        const float4 m = *(const float4*)(rp + gx0);                    \
        rows[SLOT][0] = rp[xm1];                                        \
        rows[SLOT][1] = m.x; rows[SLOT][2] = m.y;                       \
        rows[SLOT][3] = m.z; rows[SLOT][4] = m.w;                       \
        rows[SLOT][5] = rp[xp4];                                        \
    }

    // prime: rows gy0-1, gy0, gy0+1
    LOAD_ROW(0, gy0 - 1)
    LOAD_ROW(1, gy0)
    LOAD_ROW(2, gy0 + 1)

    // compute edge weight pair: d = nb - c; w = ex2(nar*d^2 + ns)
    #define EDGE2(W2, NB2, NS2, C2) {                    \
        const u64 d2 = fma2((C2), negone2, (NB2));       \
        const u64 u2 = mul2(d2, nar2);                   \
        const u64 g2 = fma2(d2, u2, (NS2));              \
        float ga, gb;  unpack2(g2, ga, gb);              \
        (W2) = pack2(ex2_approx(ga), ex2_approx(gb));    \
    }
    #define APPLY(W2, NB2, NUM2, DEN2) {                 \
        (NUM2) = fma2((W2), (NB2), (NUM2));              \
        (DEN2) = add2((DEN2), (W2));                     \
    }

    // bot-edge weight cache: w(u, dxc) for u=0..3, dxc=-1,0,+1
    u64 wm1A, w0A, wp1A, wm1B, w0B, wp1B;

    #pragma unroll
    for (int r = 0; r < FPPT; r++) {
        // prefetch next bottom row (one iteration ahead)
        if (r < FPPT - 1) LOAD_ROW((r + 3) & 3, gy0 + 2 + r)

        const float* top = rows[(r    ) & 3];
        const float* mid = rows[(r + 1) & 3];
        const float* bot = rows[(r + 2) & 3];

        // pair A = px cols 0,1 (mid[1],mid[2]); pair B = px cols 2,3 (mid[3],mid[4])
        const u64 c2A = pack2(mid[1], mid[2]);
        const u64 c2B = pack2(mid[3], mid[4]);

        // center taps (w == 1 exactly) folded into init
        u64 numA = c2A, denA = one2;
        u64 numB = c2B, denB = one2;

        // packed top-row neighbor values
        const u64 t_m1A = pack2(top[0], top[1]);
        const u64 t_0A  = pack2(top[1], top[2]);
        const u64 t_p1A = pack2(top[2], top[3]);
        const u64 t_m1B = t_p1A;                   // (top[2], top[3])
        const u64 t_0B  = pack2(top[3], top[4]);
        const u64 t_p1B = pack2(top[4], top[5]);

        if (r == 0) {
            // first row: all top edges fresh
            u64 w;
            EDGE2(w, t_m1A, ns_xy2, c2A) APPLY(w, t_m1A, numA, denA)
            EDGE2(w, t_0A,  ns_y2,  c2A) APPLY(w, t_0A,  numA, denA)
            EDGE2(w, t_p1A, ns_xy2, c2A) APPLY(w, t_p1A, numA, denA)
            EDGE2(w, t_m1B, ns_xy2, c2B) APPLY(w, t_m1B, numB, denB)
            EDGE2(w, t_0B,  ns_y2,  c2B) APPLY(w, t_0B,  numB, denB)
            EDGE2(w, t_p1B, ns_xy2, c2B) APPLY(w, t_p1B, numB, denB)
        } else {
            // cached top edges (= previous iteration's bot edges, symmetric)
            APPLY(w0A, t_0A, numA, denA)
            APPLY(w0B, t_0B, numB, denB)

            // two boundary edges not in cache: (u=-1,dxc=+1) and (u=4,dxc=-1)
            const float df1 = top[0] - mid[1];
            const float wf1 = ex2_approx(fmaf(df1, df1 * nar, -axyl));
            const float df2 = top[5] - mid[4];
            const float wf2 = ex2_approx(fmaf(df2, df2 * nar, -axyl));

            float m1Alo, m1Ahi, m1Blo, m1Bhi, p1Alo, p1Ahi, p1Blo, p1Bhi;
            unpack2(wm1A, m1Alo, m1Ahi);
            unpack2(wm1B, m1Blo, m1Bhi);
            unpack2(wp1A, p1Alo, p1Ahi);
            unpack2(wp1B, p1Blo, p1Bhi);

            // top dx=-1 taps: weights = cached (u=v-1, dxc=+1)
            { const u64 w2 = pack2(wf1,   p1Alo); APPLY(w2, t_m1A, numA, denA) }
            { const u64 w2 = pack2(p1Ahi, p1Blo); APPLY(w2, t_m1B, numB, denB) }
            // top dx=+1 taps: weights = cached (u=v+1, dxc=-1)
            { const u64 w2 = pack2(m1Ahi, m1Blo); APPLY(w2, t_p1A, numA, denA) }
            { const u64 w2 = pack2(m1Bhi, wf2);   APPLY(w2, t_p1B, numB, denB) }
        }

        // mid-row taps: 5 distinct horizontal edges shared across the 8 taps
        {
            const u64 nbAl = pack2(mid[0], mid[1]);
            const u64 nbAr = pack2(mid[2], mid[3]);
            const u64 nbBr = pack2(mid[4], mid[5]);

            // P = (e(mid0,mid1), e(mid1,mid2))
            const u64 dP = fma2(c2A, negone2, nbAl);
            const u64 gP = fma2(dP, mul2(dP, nar2), ns_x2);
            float gPl, gPh;  unpack2(gP, gPl, gPh);
            const float wPl = ex2_approx(gPl), wPh = ex2_approx(gPh);

            // Q = (e(mid2,mid3), e(mid3,mid4))
            const u64 dQ = fma2(c2B, negone2, nbAr);
            const u64 gQ = fma2(dQ, mul2(dQ, nar2), ns_x2);
            float gQl, gQh;  unpack2(gQ, gQl, gQh);
            const float wQl = ex2_approx(gQl), wQh = ex2_approx(gQh);

            // e(mid4,mid5): scalar
            const float d34 = mid[5] - mid[4];
            const float w34 = ex2_approx(fmaf(d34, d34 * nar, -axl));

            const u64 LA = pack2(wPl, wPh);    // left weights of pair A
            const u64 RA = pack2(wPh, wQl);    // right weights of pair A
            const u64 LB = pack2(wQl, wQh);    // left weights of pair B
            const u64 RB = pack2(wQh, w34);    // right weights of pair B
            APPLY(LA, nbAl, numA, denA)
            APPLY(RA, nbAr, numA, denA)
            APPLY(LB, nbAr, numB, denB)
            APPLY(RB, nbBr, numB, denB)
        }

        // bot-row taps (fresh; cache weights for next iteration's top)
        {
            const u64 b_m1A = pack2(bot[0], bot[1]);
            const u64 b_0A  = pack2(bot[1], bot[2]);
            const u64 b_p1A = pack2(bot[2], bot[3]);
            const u64 b_m1B = b_p1A;
            const u64 b_0B  = pack2(bot[3], bot[4]);
            const u64 b_p1B = pack2(bot[4], bot[5]);
            EDGE2(wm1A, b_m1A, ns_xy2, c2A) APPLY(wm1A, b_m1A, numA, denA)
            EDGE2(w0A,  b_0A,  ns_y2,  c2A) APPLY(w0A,  b_0A,  numA, denA)
            EDGE2(wp1A, b_p1A, ns_xy2, c2A) APPLY(wp1A, b_p1A, numA, denA)
            EDGE2(wm1B, b_m1B, ns_xy2, c2B) APPLY(wm1B, b_m1B, numB, denB)
            EDGE2(w0B,  b_0B,  ns_y2,  c2B) APPLY(w0B,  b_0B,  numB, denB)
            EDGE2(wp1B, b_p1B, ns_xy2, c2B) APPLY(wp1B, b_p1B, numB, denB)
        }

        float n0, n1, n2, n3, d0, d1, d2, d3;
        unpack2(numA, n0, n1); unpack2(denA, d0, d1);
        unpack2(numB, n2, n3); unpack2(denB, d2, d3);
        float4 res;
        res.x = __fdividef(n0, d0);
        res.y = __fdividef(n1, d1);
        res.z = __fdividef(n2, d2);
        res.w = __fdividef(n3, d3);
        *(float4*)(op + (gy0 + r) * W + gx0) = res;
    }
    #undef LOAD_ROW
    #undef EDGE2
    #undef APPLY
}

extern "C" void kernel_launch(void* const* d_in, const int* in_sizes, int n_in,
                              void* d_out, int out_size)
{
    const float* x         = (const float*)d_in[0];
    const float* sigma_xyz = (const float*)d_in[1];
    const float* sigma_r   = (const float*)d_in[2];
    float* out = (float*)d_out;

    const int B = in_sizes[0] / (H * W);

    float* buf0;
    float* buf1;
    cudaGetSymbolAddress((void**)&buf0, g_buf0);
    cudaGetSymbolAddress((void**)&buf1, g_buf1);

    dim3 fblock(GTX, GTY, 1);
    dim3 fgrid(W / GBLKX, H / GBLKY, B);

    bilateral_pass<<<fgrid, fblock>>>(x,    buf0, sigma_xyz, sigma_r, 0);
    bilateral_pass<<<fgrid, fblock>>>(buf0, buf1, sigma_xyz, sigma_r, 1);
    bilateral_pass<<<fgrid, fblock>>>(buf1, out,  sigma_xyz, sigma_r, 2);
}

// round 15
// speedup vs baseline: 1.3710x; 1.0177x over previous
#include <cuda_runtime.h>
#include <cstdint>

#define HW 2
#define H 512
#define W 512

// ---- geometry: 4-wide x 8-tall per thread, direct gmem ----
#define GTX 8                        // threads x (each covers 4 px)
#define GTY 8                        // threads y
#define FPPT 8                       // pixel rows per thread
#define GBLKX 32                     // px per block in x
#define GBLKY (GTY * FPPT)           // 64 px per block in y

typedef unsigned long long u64;

// scratch (allocation-free rule -> device globals)
__device__ float g_buf0[32 * H * W];
__device__ float g_buf1[32 * H * W];

__device__ __forceinline__ float ex2_approx(float x) {
    float y;
    asm("ex2.approx.ftz.f32 %0, %1;" : "=f"(y) : "f"(x));
    return y;
}

// packed f32x2 helpers (Blackwell FFMA2/FADD2/FMUL2 — only reachable via PTX)
__device__ __forceinline__ u64 pack2(float lo, float hi) {
    u64 r;
    asm("mov.b64 %0, {%1, %2};" : "=l"(r) : "f"(lo), "f"(hi));
    return r;
}
__device__ __forceinline__ void unpack2(u64 v, float& lo, float& hi) {
    asm("mov.b64 {%0, %1}, %2;" : "=f"(lo), "=f"(hi) : "l"(v));
}
__device__ __forceinline__ u64 fma2(u64 a, u64 b, u64 c) {
    u64 r;
    asm("fma.rn.f32x2 %0, %1, %2, %3;" : "=l"(r) : "l"(a), "l"(b), "l"(c));
    return r;
}
__device__ __forceinline__ u64 add2(u64 a, u64 b) {
    u64 r;
    asm("add.rn.f32x2 %0, %1, %2;" : "=l"(r) : "l"(a), "l"(b));
    return r;
}
__device__ __forceinline__ u64 mul2(u64 a, u64 b) {
    u64 r;
    asm("mul.rn.f32x2 %0, %1, %2;" : "=l"(r) : "l"(a), "l"(b));
    return r;
}
__device__ __forceinline__ void prefetch_l1(const float* p) {
    asm volatile("prefetch.global.L1 [%0];" :: "l"(p));
}

// ---------------- single kernel: adaptive 3x3 fast path + cold full-5x5 path ----------------
__global__ __launch_bounds__(GTX * GTY) void bilateral_pass(
    const float* __restrict__ in, float* __restrict__ out,
    const float* __restrict__ sigma_xyz, const float* __restrict__ sigma_r,
    int pass)
{
    const float LOG2E = 1.4426950408889634f;
    const float sx = sigma_xyz[2 * pass + 0];
    const float sy = sigma_xyz[2 * pass + 1];
    const float sr = sigma_r[pass];

    const float axn = 0.5f / (sx * sx);
    const float ayn = 0.5f / (sy * sy);
    const float axl = axn * LOG2E;               // log2-domain spatial coeffs
    const float ayl = ayn * LOG2E;
    const float ar  = (0.5f / (sr * sr)) * LOG2E;
    const float nar = -ar;
    const float axyl = axl + ayl;

    const int b   = blockIdx.z;
    const int gx0 = blockIdx.x * GBLKX + threadIdx.x * 4;     // first pixel col
    const int gy0 = blockIdx.y * GBLKY + threadIdx.y * FPPT;  // first pixel row
    const float* img = in  + (size_t)b * (H * W);
    float*       op  = out + (size_t)b * (H * W);

    // ---- adaptive truncation decision (uniform across launch) ----
    // error bound for dropping the 16 |d|=2 taps: per tap <= ws * sr * e^{-1/2}; den >= 1.
    {
        const float w1x = __expf(-axn), w4x = __expf(-4.f * axn);
        const float w1y = __expf(-ayn), w4y = __expf(-4.f * ayn);
        const float ring = 2.f * w4x * (1.f + 2.f * w1y + 2.f * w4y)
                         + 2.f * w4y * (1.f + 2.f * w1x);
        if (!(ring * 0.6065307f * sr < 1e-4f)) {
            // -------- cold path: exact full 5x5, direct gmem, minimal registers --------
            #pragma unroll 1
            for (int r = 0; r < FPPT; r++) {
                #pragma unroll 1
                for (int i = 0; i < 4; i++) {
                    const int py = gy0 + r, px = gx0 + i;
                    const float c = img[py * W + px];
                    float num = c, den = 1.0f;
                    #pragma unroll 1
                    for (int dy = -2; dy <= 2; dy++) {
                        const int yy = min(max(py + dy, 0), H - 1);
                        #pragma unroll 1
                        for (int dx = -2; dx <= 2; dx++) {
                            if ((dx | dy) == 0) continue;
                            const int xx = min(max(px + dx, 0), W - 1);
                            const float nb = img[yy * W + xx];
                            const float d  = nb - c;
                            const float s  = fmaf((float)(dx * dx), axl,
                                                  (float)(dy * dy) * ayl);
                            const float w  = ex2_approx(fmaf(d * d, nar, -s));
                            num = fmaf(w, nb, num);
                            den += w;
                        }
                    }
                    op[py * W + px] = __fdividef(num, den);
                }
            }
            return;
        }
    }

    // -------- fast path: 3x3, packed taps + symmetric-edge weight caches --------
    const u64 nar2    = pack2(nar, nar);
    const u64 negone2 = pack2(-1.0f, -1.0f);
    const u64 one2    = pack2(1.0f, 1.0f);
    const u64 ns_xy2  = pack2(-axyl, -axyl);   // |dx|=1,|dy|=1
    const u64 ns_y2   = pack2(-ayl,  -ayl);    // dx=0,|dy|=1
    const u64 ns_x2   = pack2(-axl,  -axl);    // |dx|=1,dy=0

    // clamped edge columns (only ones that can go OOB)
    const int xm1 = max(gx0 - 1, 0);
    const int xp4 = min(gx0 + 4, W - 1);

    // 4-slot row ring, 6 floats per row (cols gx0-1 .. gx0+4)
    float rows[4][6];

    #define LOAD_ROW(SLOT, RY) {                                        \
        const int ryc = min(max((RY), 0), H - 1);                       \
        const float* rp = img + ryc * W;                                \
        const float4 m = *(const float4*)(rp + gx0);                    \
        rows[SLOT][0] = rp[xm1];                                        \
        rows[SLOT][1] = m.x; rows[SLOT][2] = m.y;                       \
        rows[SLOT][3] = m.z; rows[SLOT][4] = m.w;                       \
        rows[SLOT][5] = rp[xp4];                                        \
    }
    // L1 prefetch of a future row (zero register cost; covers L2 latency)
    #define PREFETCH_ROW(RY) {                                          \
        const int ryc = min((RY), H - 1);                               \
        prefetch_l1(img + ryc * W + gx0);                               \
    }

    // prefetch the rows the first two loop iterations will LDG
    PREFETCH_ROW(gy0 + 2)
    PREFETCH_ROW(gy0 + 3)

    // prime: rows gy0-1, gy0, gy0+1
    LOAD_ROW(0, gy0 - 1)
    LOAD_ROW(1, gy0)
    LOAD_ROW(2, gy0 + 1)

    // compute edge weight pair: d = nb - c; w = ex2(nar*d^2 + ns)
    #define EDGE2(W2, NB2, NS2, C2) {                    \
        const u64 d2 = fma2((C2), negone2, (NB2));       \
        const u64 u2 = mul2(d2, nar2);                   \
        const u64 g2 = fma2(d2, u2, (NS2));              \
        float ga, gb;  unpack2(g2, ga, gb);              \
        (W2) = pack2(ex2_approx(ga), ex2_approx(gb));    \
    }
    #define APPLY(W2, NB2, NUM2, DEN2) {                 \
        (NUM2) = fma2((W2), (NB2), (NUM2));              \
        (DEN2) = add2((DEN2), (W2));                     \
    }

    // bot-edge weight cache: w(u, dxc) for u=0..3, dxc=-1,0,+1
    u64 wm1A, w0A, wp1A, wm1B, w0B, wp1B;

    #pragma unroll
    for (int r = 0; r < FPPT; r++) {
        // L1-prefetch 2 iterations ahead of the register load below
        if (r < FPPT - 3) PREFETCH_ROW(gy0 + 4 + r)
        // register prefetch: next bottom row (one iteration ahead; L1 hit)
        if (r < FPPT - 1) LOAD_ROW((r + 3) & 3, gy0 + 2 + r)

        const float* top = rows[(r    ) & 3];
        const float* mid = rows[(r + 1) & 3];
        const float* bot = rows[(r + 2) & 3];

        // pair A = px cols 0,1 (mid[1],mid[2]); pair B = px cols 2,3 (mid[3],mid[4])
        const u64 c2A = pack2(mid[1], mid[2]);
        const u64 c2B = pack2(mid[3], mid[4]);

        // center taps (w == 1 exactly) folded into init
        u64 numA = c2A, denA = one2;
        u64 numB = c2B, denB = one2;

        // packed top-row neighbor values
        const u64 t_m1A = pack2(top[0], top[1]);
        const u64 t_0A  = pack2(top[1], top[2]);
        const u64 t_p1A = pack2(top[2], top[3]);
        const u64 t_m1B = t_p1A;                   // (top[2], top[3])
        const u64 t_0B  = pack2(top[3], top[4]);
        const u64 t_p1B = pack2(top[4], top[5]);

        if (r == 0) {
            // first row: all top edges fresh
            u64 w;
            EDGE2(w, t_m1A, ns_xy2, c2A) APPLY(w, t_m1A, numA, denA)
            EDGE2(w, t_0A,  ns_y2,  c2A) APPLY(w, t_0A,  numA, denA)
            EDGE2(w, t_p1A, ns_xy2, c2A) APPLY(w, t_p1A, numA, denA)
            EDGE2(w, t_m1B, ns_xy2, c2B) APPLY(w, t_m1B, numB, denB)
            EDGE2(w, t_0B,  ns_y2,  c2B) APPLY(w, t_0B,  numB, denB)
            EDGE2(w, t_p1B, ns_xy2, c2B) APPLY(w, t_p1B, numB, denB)
        } else {
            // cached top edges (= previous iteration's bot edges, symmetric)
            APPLY(w0A, t_0A, numA, denA)
            APPLY(w0B, t_0B, numB, denB)

            // two boundary edges not in cache: (u=-1,dxc=+1) and (u=4,dxc=-1)
            const float df1 = top[0] - mid[1];
            const float wf1 = ex2_approx(fmaf(df1, df1 * nar, -axyl));
            const float df2 = top[5] - mid[4];
            const float wf2 = ex2_approx(fmaf(df2, df2 * nar, -axyl));

            float m1Alo, m1Ahi, m1Blo, m1Bhi, p1Alo, p1Ahi, p1Blo, p1Bhi;
            unpack2(wm1A, m1Alo, m1Ahi);
            unpack2(wm1B, m1Blo, m1Bhi);
            unpack2(wp1A, p1Alo, p1Ahi);
            unpack2(wp1B, p1Blo, p1Bhi);

            // top dx=-1 taps: weights = cached (u=v-1, dxc=+1)
            { const u64 w2 = pack2(wf1,   p1Alo); APPLY(w2, t_m1A, numA, denA) }
            { const u64 w2 = pack2(p1Ahi, p1Blo); APPLY(w2, t_m1B, numB, denB) }
            // top dx=+1 taps: weights = cached (u=v+1, dxc=-1)
            { const u64 w2 = pack2(m1Ahi, m1Blo); APPLY(w2, t_p1A, numA, denA) }
            { const u64 w2 = pack2(m1Bhi, wf2);   APPLY(w2, t_p1B, numB, denB) }
        }

        // mid-row taps: 5 distinct horizontal edges shared across the 8 taps
        {
            const u64 nbAl = pack2(mid[0], mid[1]);
            const u64 nbAr = pack2(mid[2], mid[3]);
            const u64 nbBr = pack2(mid[4], mid[5]);

            // P = (e(mid0,mid1), e(mid1,mid2))
            const u64 dP = fma2(c2A, negone2, nbAl);
            const u64 gP = fma2(dP, mul2(dP, nar2), ns_x2);
            float gPl, gPh;  unpack2(gP, gPl, gPh);
            const float wPl = ex2_approx(gPl), wPh = ex2_approx(gPh);

            // Q = (e(mid2,mid3), e(mid3,mid4))
            const u64 dQ = fma2(c2B, negone2, nbAr);
            const u64 gQ = fma2(dQ, mul2(dQ, nar2), ns_x2);
            float gQl, gQh;  unpack2(gQ, gQl, gQh);
            const float wQl = ex2_approx(gQl), wQh = ex2_approx(gQh);

            // e(mid4,mid5): scalar
            const float d34 = mid[5] - mid[4];
            const float w34 = ex2_approx(fmaf(d34, d34 * nar, -axl));

            const u64 LA = pack2(wPl, wPh);    // left weights of pair A
            const u64 RA = pack2(wPh, wQl);    // right weights of pair A
            const u64 LB = pack2(wQl, wQh);    // left weights of pair B
            const u64 RB = pack2(wQh, w34);    // right weights of pair B
            APPLY(LA, nbAl, numA, denA)
            APPLY(RA, nbAr, numA, denA)
            APPLY(LB, nbAr, numB, denB)
            APPLY(RB, nbBr, numB, denB)
        }

        // bot-row taps (fresh; cache weights for next iteration's top)
        {
            const u64 b_m1A = pack2(bot[0], bot[1]);
            const u64 b_0A  = pack2(bot[1], bot[2]);
            const u64 b_p1A = pack2(bot[2], bot[3]);
            const u64 b_m1B = b_p1A;
            const u64 b_0B  = pack2(bot[3], bot[4]);
            const u64 b_p1B = pack2(bot[4], bot[5]);
            EDGE2(wm1A, b_m1A, ns_xy2, c2A) APPLY(wm1A, b_m1A, numA, denA)
            EDGE2(w0A,  b_0A,  ns_y2,  c2A) APPLY(w0A,  b_0A,  numA, denA)
            EDGE2(wp1A, b_p1A, ns_xy2, c2A) APPLY(wp1A, b_p1A, numA, denA)
            EDGE2(wm1B, b_m1B, ns_xy2, c2B) APPLY(wm1B, b_m1B, numB, denB)
            EDGE2(w0B,  b_0B,  ns_y2,  c2B) APPLY(w0B,  b_0B,  numB, denB)
            EDGE2(wp1B, b_p1B, ns_xy2, c2B) APPLY(wp1B, b_p1B, numB, denB)
        }

        float n0, n1, n2, n3, d0, d1, d2, d3;
        unpack2(numA, n0, n1); unpack2(denA, d0, d1);
        unpack2(numB, n2, n3); unpack2(denB, d2, d3);
        float4 res;
        res.x = __fdividef(n0, d0);
        res.y = __fdividef(n1, d1);
        res.z = __fdividef(n2, d2);
        res.w = __fdividef(n3, d3);
        *(float4*)(op + (gy0 + r) * W + gx0) = res;
    }
    #undef LOAD_ROW
    #undef PREFETCH_ROW
    #undef EDGE2
    #undef APPLY
}

extern "C" void kernel_launch(void* const* d_in, const int* in_sizes, int n_in,
                              void* d_out, int out_size)
{
    const float* x         = (const float*)d_in[0];
    const float* sigma_xyz = (const float*)d_in[1];
    const float* sigma_r   = (const float*)d_in[2];
    float* out = (float*)d_out;

    const int B = in_sizes[0] / (H * W);

    float* buf0;
    float* buf1;
    cudaGetSymbolAddress((void**)&buf0, g_buf0);
    cudaGetSymbolAddress((void**)&buf1, g_buf1);

    dim3 fblock(GTX, GTY, 1);
    dim3 fgrid(W / GBLKX, H / GBLKY, B);

    bilateral_pass<<<fgrid, fblock>>>(x,    buf0, sigma_xyz, sigma_r, 0);
    bilateral_pass<<<fgrid, fblock>>>(buf0, buf1, sigma_xyz, sigma_r, 1);
    bilateral_pass<<<fgrid, fblock>>>(buf1, out,  sigma_xyz, sigma_r, 2);
}